// round 7
// baseline (speedup 1.0000x reference)
#include <cuda_runtime.h>
#include <cuda_bf16.h>
#include <cstdint>

// Problem constants: B=8, S=4096, H=1024, SEG_PER_EX=64, NUM_SEG=512, P=4096
#define TOKS   32768
#define HDIM   1024
#define NSEG   512
#define SEGEX  64
#define NPAIR  4096
#define KROW   2048             // per-row K extent of A_cat/B_cat: [hi(1024) | lo(1024)]
#define NCHUNK 32               // 16 chunks vs B_hi (A hi+lo), 16 chunks vs B_lo (A hi)
#define NSTAGE 3
#define STAGE_BYTES 32768       // A1 8KB + A2 8KB + B 16KB
#define SMEM_TOTAL (NSTAGE * STAGE_BYTES)   // 98304

// -------- device scratch (static; no cudaMalloc allowed) --------
__device__ __align__(128) __nv_bfloat16 g_Acat[NSEG * KROW];       // 2 MB  [m][ hi | lo ]
__device__ __align__(128) __nv_bfloat16 g_Bcat[2 * HDIM * KROW];   // 8 MB  [n][ hi | lo ]
__device__ float g_sums[NSEG * HDIM];                              // 2 MB  pooled partial sums
__device__ float g_Hb[NSEG * 2 * HDIM];                            // 4 MB  [s][0:H]=H1, [s][H:2H]=H2
__device__ int   g_start[NSEG];
__device__ int   g_end[NSEG];

__device__ __forceinline__ uint32_t smem_u32(const void* p) {
    uint32_t a;
    asm("{ .reg .u64 t; cvta.to.shared.u64 t, %1; cvt.u32.u64 %0, t; }" : "=r"(a) : "l"(p));
    return a;
}
#define CP_ASYNC16(dst, src) \
    asm volatile("cp.async.cg.shared.global [%0], [%1], 16;" :: "r"(dst), "l"(src))
#define CP_COMMIT() asm volatile("cp.async.commit_group;")
#define CP_WAIT(N)  asm volatile("cp.async.wait_group %0;" :: "n"(N))

#define LDMATRIX_X4(r0, r1, r2, r3, addr) \
    asm volatile("ldmatrix.sync.aligned.m8n8.x4.shared.b16 {%0,%1,%2,%3}, [%4];" \
        : "=r"(r0), "=r"(r1), "=r"(r2), "=r"(r3) : "r"(addr))

#define MMA_BF16(c0, c1, c2, c3, a0, a1, a2, a3, b0, b1) \
    asm volatile("mma.sync.aligned.m16n8k16.row.col.f32.bf16.bf16.f32 " \
        "{%0,%1,%2,%3}, {%4,%5,%6,%7}, {%8,%9}, {%0,%1,%2,%3};" \
        : "+f"(c0), "+f"(c1), "+f"(c2), "+f"(c3) \
        : "r"(a0), "r"(a1), "r"(a2), "r"(a3), "r"(b0), "r"(b1))

// smem tile addressing: rows of 64 bf16 = 128 B; 16B-unit column swizzled by row
__device__ __forceinline__ uint32_t sw_off(int row, int c16) {
    return (uint32_t)(row * 128 + ((c16 ^ (row & 7)) << 4));
}

// ---------------------------------------------------------------------------
// 0) init: zero pooled sums + segment bounds
// ---------------------------------------------------------------------------
__global__ void init_kernel() {
    int i = blockIdx.x * blockDim.x + threadIdx.x;
    if (i < NSEG) { g_start[i] = 0; g_end[i] = 0; }
    for (int j = i; j < NSEG * HDIM; j += gridDim.x * blockDim.x) g_sums[j] = 0.f;
}

// ---------------------------------------------------------------------------
// 1) segment boundaries (flat_seg globally sorted -> contiguous token ranges)
// ---------------------------------------------------------------------------
__global__ void bounds_kernel(const int* __restrict__ seg) {
    int i = blockIdx.x * blockDim.x + threadIdx.x;
    if (i >= TOKS) return;
    int s  = seg[i] + (i >> 12) * SEGEX;
    int sp = (i > 0)        ? (seg[i - 1] + ((i - 1) >> 12) * SEGEX) : -1;
    int sn = (i < TOKS - 1) ? (seg[i + 1] + ((i + 1) >> 12) * SEGEX) : -1;
    if (s != sp) g_start[s] = i;
    if (s != sn) g_end[s]   = i + 1;
}

// ---------------------------------------------------------------------------
// 2) token-chunk-parallel pooling: block = (h-chunk 0..3, token-chunk 0..127).
//    Perfect load balance; 8-deep batched loads for MLP; run-detected
//    atomicAdd partial sums (~1 atomic per ~64 tokens per thread).
// ---------------------------------------------------------------------------
__global__ __launch_bounds__(256) void pool2_kernel(const float* __restrict__ tok,
                                                    const int* __restrict__ seg) {
    __shared__ int sseg[256];
    const int t0 = blockIdx.y << 8;                 // token chunk start
    const int ex = t0 >> 12;                        // example id (chunk within one row)
    sseg[threadIdx.x] = seg[t0 + threadIdx.x] + ex * SEGEX;
    __syncthreads();
    const int h = (blockIdx.x << 8) + threadIdx.x;
    const float* p = tok + (size_t)t0 * HDIM + h;
    float acc = 0.f;
    int cur = sseg[0];
    for (int t = 0; t < 256; t += 8) {
        float v[8];
        #pragma unroll
        for (int j = 0; j < 8; ++j) v[j] = p[(size_t)(t + j) * HDIM];
        #pragma unroll
        for (int j = 0; j < 8; ++j) {
            int sg = sseg[t + j];
            if (sg != cur) { atomicAdd(&g_sums[(size_t)cur * HDIM + h], acc); acc = 0.f; cur = sg; }
            acc += v[j];
        }
    }
    atomicAdd(&g_sums[(size_t)cur * HDIM + h], acc);
}

// ---------------------------------------------------------------------------
// 2b) finalize: mean + bf16 hi/lo split -> A_cat[m][ hi | lo ]
// ---------------------------------------------------------------------------
__global__ __launch_bounds__(256) void finalizeA_kernel() {
    int s = blockIdx.y;
    int h = (blockIdx.x << 8) + threadIdx.x;
    int cnt = g_end[s] - g_start[s];
    float mean = g_sums[(size_t)s * HDIM + h] / (float)(cnt > 0 ? cnt : 1);
    __nv_bfloat16 hi = __float2bfloat16(mean);
    __nv_bfloat16 lo = __float2bfloat16(mean - __bfloat162float(hi));
    g_Acat[(size_t)s * KROW + h]        = hi;
    g_Acat[(size_t)s * KROW + HDIM + h] = lo;
}

// ---------------------------------------------------------------------------
// 2c) B_cat[n][k] = Wcat[k][n] split into [hi | lo], via smem transpose.
//     Wcat[k,n] = n<H ? W1[k*H + n] : W1[(H+k)*H + (n-H)]
// ---------------------------------------------------------------------------
__global__ __launch_bounds__(256) void convB_kernel(const float* __restrict__ W1) {
    __shared__ float s[64][65];
    int n0 = blockIdx.x << 6;
    int k0 = blockIdx.y << 6;
    int t = threadIdx.x;
    const float* Wb = W1 + ((n0 >= HDIM) ? ((size_t)HDIM * HDIM - HDIM) : 0);
    {
        int kl = t >> 2, nq = (t & 3) << 4;
        const float4* src = (const float4*)(Wb + (size_t)(k0 + kl) * HDIM + n0 + nq);
        #pragma unroll
        for (int j = 0; j < 4; ++j) {
            float4 v = src[j];
            s[kl][nq + 4 * j + 0] = v.x;
            s[kl][nq + 4 * j + 1] = v.y;
            s[kl][nq + 4 * j + 2] = v.z;
            s[kl][nq + 4 * j + 3] = v.w;
        }
    }
    __syncthreads();
    {
        int nl = t >> 2, kq = (t & 3) << 4;
        __nv_bfloat16 hi[16], lo[16];
        #pragma unroll
        for (int j = 0; j < 16; ++j) {
            float v = s[kq + j][nl];
            hi[j] = __float2bfloat16(v);
            lo[j] = __float2bfloat16(v - __bfloat162float(hi[j]));
        }
        size_t base = (size_t)(n0 + nl) * KROW + k0 + kq;
        uint4* dhi = (uint4*)(g_Bcat + base);
        uint4* dlo = (uint4*)(g_Bcat + base + HDIM);
        dhi[0] = ((const uint4*)hi)[0]; dhi[1] = ((const uint4*)hi)[1];
        dlo[0] = ((const uint4*)lo)[0]; dlo[1] = ((const uint4*)lo)[1];
    }
}

// ---------------------------------------------------------------------------
// 3) mma.sync GEMM with B-reuse split-K:
//    chunks 0..15 : B=Bhi[k], compute A_hi·B + A_lo·B (two A tiles, one B tile)
//    chunks 16..31: B=Blo[k], compute A_hi·B
//    CTA tile 64(m) x 128(n), 8 warps (2x4), warp tile 32x32,
//    3-stage cp.async pipeline (A1 8K + A2 8K + B 16K per stage).
// ---------------------------------------------------------------------------
__global__ __launch_bounds__(256) void mma_gemm_kernel() {
    extern __shared__ __align__(128) char smem[];
    const uint32_t sb = smem_u32(smem);
    const int tid  = threadIdx.x;
    const int wid  = tid >> 5, lane = tid & 31;
    const int wm   = wid >> 2;
    const int wn   = wid & 3;
    const int m0   = blockIdx.y << 6;   // 512/64 = 8
    const int n0   = blockIdx.x << 7;   // 2048/128 = 16

    // ---- cp.async mapping: A (64 rows x 8 units): 2 units/thread; B (128 x 8): 4/thread
    const int ra0 = tid >> 3, ca = tid & 7;
    const int ra1 = ra0 + 32;
    const char* gA0 = (const char*)(g_Acat + (size_t)(m0 + ra0) * KROW) + ca * 16;
    const char* gA1 = (const char*)(g_Acat + (size_t)(m0 + ra1) * KROW) + ca * 16;
    const uint32_t oA0 = sw_off(ra0, ca), oA1 = sw_off(ra1, ca);
    const char* gB[4];
    uint32_t oB[4];
    #pragma unroll
    for (int j = 0; j < 4; ++j) {
        int u = tid + 256 * j;
        int nr = u >> 3, c = u & 7;
        gB[j] = (const char*)(g_Bcat + (size_t)(n0 + nr) * KROW) + c * 16;
        oB[j] = 16384 + sw_off(nr, c);
    }

    float c[2][4][4];
    #pragma unroll
    for (int tm = 0; tm < 2; ++tm)
        #pragma unroll
        for (int tn = 0; tn < 4; ++tn)
            #pragma unroll
            for (int q = 0; q < 4; ++q) c[tm][tn][q] = 0.f;

    const int arow[2] = { wm * 32 + (lane & 15), wm * 32 + 16 + (lane & 15) };
    const int ac16    = lane >> 4;
    const int brow[2] = { wn * 32 + (lane & 7) + ((lane >> 4) << 3),
                          wn * 32 + 16 + (lane & 7) + ((lane >> 4) << 3) };
    const int bc16    = (lane >> 3) & 1;

    // ---- issue chunk j into stage j%3
    auto issue = [&](int j) {
        uint32_t s0 = sb + (uint32_t)(j % NSTAGE) * STAGE_BYTES;
        int aoff = ((j < 16) ? j : (j - 16)) * 128;           // A_hi k-offset bytes
        CP_ASYNC16(s0 + oA0, gA0 + aoff);
        CP_ASYNC16(s0 + oA1, gA1 + aoff);
        if (j < 16) {                                          // A_lo tile (pairs with B_hi)
            CP_ASYNC16(s0 + 8192 + oA0, gA0 + 2048 + j * 128);
            CP_ASYNC16(s0 + 8192 + oA1, gA1 + 2048 + j * 128);
        }
        int boff = (j < 16) ? j * 128 : 2048 + (j - 16) * 128; // B_hi then B_lo
        #pragma unroll
        for (int q = 0; q < 4; ++q) CP_ASYNC16(s0 + oB[q], gB[q] + boff);
        CP_COMMIT();
    };

    issue(0);
    issue(1);

    int stage = 0;
    for (int i = 0; i < NCHUNK; ++i) {
        if (i + 2 < NCHUNK) issue(i + 2);
        if (i + 2 < NCHUNK)      CP_WAIT(2);
        else if (i + 1 < NCHUNK) CP_WAIT(1);
        else                     CP_WAIT(0);
        __syncthreads();

        const uint32_t sA1 = sb + stage * STAGE_BYTES;
        const uint32_t sA2 = sA1 + 8192;
        const uint32_t sB  = sA1 + 16384;
        const bool dual = (i < 16);
        #pragma unroll
        for (int ks = 0; ks < 4; ++ks) {
            const int c16b = ks << 1;
            uint32_t a1[2][4], a2[2][4], b[2][4];
            #pragma unroll
            for (int tm = 0; tm < 2; ++tm) {
                LDMATRIX_X4(a1[tm][0], a1[tm][1], a1[tm][2], a1[tm][3],
                            sA1 + sw_off(arow[tm], c16b + ac16));
            }
            if (dual) {
                #pragma unroll
                for (int tm = 0; tm < 2; ++tm) {
                    LDMATRIX_X4(a2[tm][0], a2[tm][1], a2[tm][2], a2[tm][3],
                                sA2 + sw_off(arow[tm], c16b + ac16));
                }
            }
            #pragma unroll
            for (int np = 0; np < 2; ++np) {
                LDMATRIX_X4(b[np][0], b[np][1], b[np][2], b[np][3],
                            sB + sw_off(brow[np], c16b + bc16));
            }
            #pragma unroll
            for (int tm = 0; tm < 2; ++tm) {
                #pragma unroll
                for (int np = 0; np < 2; ++np) {
                    MMA_BF16(c[tm][2*np+0][0], c[tm][2*np+0][1], c[tm][2*np+0][2], c[tm][2*np+0][3],
                             a1[tm][0], a1[tm][1], a1[tm][2], a1[tm][3], b[np][0], b[np][1]);
                    MMA_BF16(c[tm][2*np+1][0], c[tm][2*np+1][1], c[tm][2*np+1][2], c[tm][2*np+1][3],
                             a1[tm][0], a1[tm][1], a1[tm][2], a1[tm][3], b[np][2], b[np][3]);
                }
            }
            if (dual) {
                #pragma unroll
                for (int tm = 0; tm < 2; ++tm) {
                    #pragma unroll
                    for (int np = 0; np < 2; ++np) {
                        MMA_BF16(c[tm][2*np+0][0], c[tm][2*np+0][1], c[tm][2*np+0][2], c[tm][2*np+0][3],
                                 a2[tm][0], a2[tm][1], a2[tm][2], a2[tm][3], b[np][0], b[np][1]);
                        MMA_BF16(c[tm][2*np+1][0], c[tm][2*np+1][1], c[tm][2*np+1][2], c[tm][2*np+1][3],
                                 a2[tm][0], a2[tm][1], a2[tm][2], a2[tm][3], b[np][2], b[np][3]);
                    }
                }
            }
        }
        __syncthreads();
        stage = (stage + 1 == NSTAGE) ? 0 : stage + 1;
    }

    // ---- epilogue
    const int g  = lane >> 2;
    const int tg = lane & 3;
    #pragma unroll
    for (int tm = 0; tm < 2; ++tm) {
        int row = m0 + wm * 32 + tm * 16 + g;
        #pragma unroll
        for (int tn = 0; tn < 4; ++tn) {
            int col = n0 + wn * 32 + tn * 8 + 2 * tg;
            *(float2*)(g_Hb + (size_t)row * (2 * HDIM) + col)       = make_float2(c[tm][tn][0], c[tm][tn][1]);
            *(float2*)(g_Hb + (size_t)(row + 8) * (2 * HDIM) + col) = make_float2(c[tm][tn][2], c[tm][tn][3]);
        }
    }
}

// ---------------------------------------------------------------------------
// 4) per-pair epilogue: logit = sum_j relu(H1[i0,j] + H2[i1,j] + b1[j]) * W2[j] + b2
// ---------------------------------------------------------------------------
__global__ __launch_bounds__(256) void pair_kernel(const int* __restrict__ pair_idx,
                                                   const float* __restrict__ b1,
                                                   const float* __restrict__ W2,
                                                   const float* __restrict__ b2,
                                                   float* __restrict__ out) {
    int p = (blockIdx.x << 3) + (threadIdx.x >> 5);
    int lane = threadIdx.x & 31;
    int i0 = pair_idx[2 * p];
    int i1 = pair_idx[2 * p + 1];
    const float4* h0 = (const float4*)(g_Hb + (size_t)i0 * (2 * HDIM));
    const float4* h1 = (const float4*)(g_Hb + (size_t)i1 * (2 * HDIM) + HDIM);
    const float4* B1 = (const float4*)b1;
    const float4* w2 = (const float4*)W2;
    float acc = 0.f;
    #pragma unroll
    for (int j = lane; j < HDIM / 4; j += 32) {
        float4 x0 = h0[j], x1 = h1[j], bb = B1[j], ww = w2[j];
        acc = fmaf(fmaxf(x0.x + x1.x + bb.x, 0.f), ww.x, acc);
        acc = fmaf(fmaxf(x0.y + x1.y + bb.y, 0.f), ww.y, acc);
        acc = fmaf(fmaxf(x0.z + x1.z + bb.z, 0.f), ww.z, acc);
        acc = fmaf(fmaxf(x0.w + x1.w + bb.w, 0.f), ww.w, acc);
    }
    #pragma unroll
    for (int o = 16; o; o >>= 1) acc += __shfl_xor_sync(0xffffffffu, acc, o);
    if (lane == 0) out[p] = acc + b2[0];
}

// ---------------------------------------------------------------------------
extern "C" void kernel_launch(void* const* d_in, const int* in_sizes, int n_in,
                              void* d_out, int out_size) {
    const float* seq  = (const float*)d_in[0];
    const int*   seg  = (const int*)d_in[1];
    const int*   pidx = (const int*)d_in[2];
    const float* W1   = (const float*)d_in[3];
    const float* b1   = (const float*)d_in[4];
    const float* W2   = (const float*)d_in[5];
    const float* b2   = (const float*)d_in[6];
    float* out = (float*)d_out;

    cudaFuncSetAttribute(mma_gemm_kernel, cudaFuncAttributeMaxDynamicSharedMemorySize, SMEM_TOTAL);

    init_kernel<<<512, 256>>>();
    bounds_kernel<<<TOKS / 256, 256>>>(seg);
    convB_kernel<<<dim3(2 * HDIM / 64, HDIM / 64), 256>>>(W1);
    pool2_kernel<<<dim3(HDIM / 256, TOKS / 256), 256>>>(seq, seg);
    finalizeA_kernel<<<dim3(HDIM / 256, NSEG), 256>>>();
    mma_gemm_kernel<<<dim3(2 * HDIM / 128, NSEG / 64), 256, SMEM_TOTAL>>>();
    pair_kernel<<<NPAIR / 8, 256>>>(pidx, b1, W2, b2, out);
}